// round 10
// baseline (speedup 1.0000x reference)
#include <cuda_runtime.h>
#include <math.h>

// ---------------- Problem constants ----------------
#define WE 300
#define TE 10
#define SL 24
#define NT1 6
#define UT 3
#define H_LSTM 75          // WE/4
#define H_GRU 77           // (WE+TE)/4
#define CLS 27
#define D_IN 7210          // SL*WE + TE
#define BATCH 256
#define NSEQ 4608          // LSTM scan length
#define LSTM_B 24          // independent LSTM sequences
#define G4 300             // 4*H_LSTM
#define G3 231             // 3*H_GRU
#define CTXF 310           // WE+TE

// GEMM tiling
#define BM 128
#define BN 160
#define BK 20
#define NKT 15             // 300 / 20, exact
#define MCHUNKS 864        // 110592 / 128
#define NBLK_GEMM 1728     // MCHUNKS * 2

// LSTM X-prefetch depth (register ring, unrolled)
#define PF 8               // 4608 % 8 == 0

// ---------------- Scratch ----------------
__device__ float g_X[(long)NSEQ * LSTM_B * G4];     // ~132.7 MB
__device__ float g_H[(long)NSEQ * LSTM_B * H_LSTM]; // only t%18>=12 written
__device__ float g_ctx[BATCH * CTXF];
__device__ float g_XG[BATCH * G3];
__device__ float g_seqlast[BATCH * H_GRU];
__device__ int   g_flag[MCHUNKS];                   // per-M-chunk done count (target 2)

// ---------------- f32x2 packed helpers ----------------
__device__ __forceinline__ unsigned long long pack2(float lo, float hi) {
    unsigned long long r;
    asm("mov.b64 %0, {%1, %2};" : "=l"(r) : "f"(lo), "f"(hi));
    return r;
}
__device__ __forceinline__ float2 unpack2(unsigned long long v) {
    float2 f;
    asm("mov.b64 {%0, %1}, %2;" : "=f"(f.x), "=f"(f.y) : "l"(v));
    return f;
}
#define FMA2(d, a, b, c) \
    asm("fma.rn.f32x2 %0, %1, %2, %3;" : "=l"(d) : "l"(a), "l"(b), "l"(c))
#define ADD2(d, a, b) \
    asm("add.rn.f32x2 %0, %1, %2;" : "=l"(d) : "l"(a), "l"(b))

// ---------------- Fast activation helpers (MUFU-based, rel err ~1e-6) ----
__device__ __forceinline__ float sigmoidf_(float x) {
    return __fdividef(1.0f, 1.0f + __expf(-x));
}
__device__ __forceinline__ float tanhf_(float x) {
    return __fdividef(2.0f, 1.0f + __expf(-2.0f * x)) - 1.0f;
}

// ---------------- Flag reset ----------------
__global__ void init_flags_kernel() {
    if (threadIdx.x < MCHUNKS) g_flag[threadIdx.x] = 0;
}

// ---------------- Dummy (slots the fused kernel into ncu's capture) ------
__global__ void dummy_kernel() {}

// ---------------- Shared-memory overlays ----------------
struct GemmSmem {
    unsigned long long Bs2[BK][BN];   // B dup'd {b,b}: 25600 B
    float As[BK][BM];                 // A transposed [k][m]: 10240 B
};
struct LstmSmem {
    float h[80];                      // h[75..79] stay 0
};

// =====================================================================
// FUSED kernel: blocks 0..23 = LSTM consumers (gate-interleaved, ONE
// barrier per step, shuffle-based gate gather), blocks 24.. = GEMM.
// =====================================================================
__global__ __launch_bounds__(320, 1) void fused_kernel(
    const float* __restrict__ A,      // inputs
    const float* __restrict__ W,      // lstm_W 300x300
    const float* __restrict__ bias,   // lstm_b 300
    const float* __restrict__ U)      // lstm_U 75x300
{
    __shared__ __align__(16) char smbuf[sizeof(GemmSmem)];
    const int tid = threadIdx.x;

    if (blockIdx.x >= LSTM_B) {
        // ================= GEMM producer =================
        GemmSmem& G = *reinterpret_cast<GemmSmem*>(smbuf);
        const int g = blockIdx.x - LSTM_B;
        const int mchunk = g >> 1;
        const int row0 = mchunk * BM;
        const int col0 = (g & 1) * BN;    // 0 or 160
        const int tr = tid / 20;          // 0..15 -> 8 M rows (4 pairs)
        const int tc = tid % 20;          // 0..19 -> 8 N cols

        long abase[4]; int acol[4]; int arow_s[4];
#pragma unroll
        for (int i = 0; i < 4; i++) {
            int idx = tid + i * 320;
            arow_s[i] = idx / 10;
            int rr = row0 + arow_s[i];
            abase[i] = (long)rr * 300 + (rr / 24) * 10;
            acol[i]  = (idx % 10) * 2;
        }
        int bkk[5], bnn[5];
#pragma unroll
        for (int i = 0; i < 5; i++) {
            int idx = tid + i * 320;
            bkk[i] = idx / 80;
            bnn[i] = (idx % 80) * 2;
        }

        unsigned long long acc[4][8];
#pragma unroll
        for (int p = 0; p < 4; p++)
#pragma unroll
            for (int q = 0; q < 8; q++) acc[p][q] = 0ull;

        float2 Ar[4], Br[5];
#define LOADT(K0) do {                                                        \
        _Pragma("unroll")                                                     \
        for (int i = 0; i < 4; i++)                                           \
            Ar[i] = *(const float2*)(A + abase[i] + (K0) + acol[i]);          \
        _Pragma("unroll")                                                     \
        for (int i = 0; i < 5; i++) {                                         \
            int gc = col0 + bnn[i];                                           \
            Br[i] = (gc < 300)                                                \
                  ? *(const float2*)(W + (long)((K0) + bkk[i]) * 300 + gc)    \
                  : make_float2(0.f, 0.f);                                    \
        }                                                                     \
    } while (0)

        LOADT(0);
        for (int kt = 0; kt < NKT; kt++) {
            __syncthreads();
#pragma unroll
            for (int i = 0; i < 4; i++) {
                G.As[acol[i]][arow_s[i]]     = Ar[i].x;
                G.As[acol[i] + 1][arow_s[i]] = Ar[i].y;
            }
#pragma unroll
            for (int i = 0; i < 5; i++) {
                G.Bs2[bkk[i]][bnn[i]]     = pack2(Br[i].x, Br[i].x);
                G.Bs2[bkk[i]][bnn[i] + 1] = pack2(Br[i].y, Br[i].y);
            }
            __syncthreads();
            if (kt + 1 < NKT) LOADT((kt + 1) * BK);

#pragma unroll
            for (int kk = 0; kk < BK; kk++) {
                ulonglong2 a01 = *(const ulonglong2*)&G.As[kk][tr * 8];
                ulonglong2 a23 = *(const ulonglong2*)&G.As[kk][tr * 8 + 4];
                ulonglong2 b01 = *(const ulonglong2*)&G.Bs2[kk][tc * 8];
                ulonglong2 b23 = *(const ulonglong2*)&G.Bs2[kk][tc * 8 + 2];
                ulonglong2 b45 = *(const ulonglong2*)&G.Bs2[kk][tc * 8 + 4];
                ulonglong2 b67 = *(const ulonglong2*)&G.Bs2[kk][tc * 8 + 6];
                unsigned long long b[8] = {b01.x, b01.y, b23.x, b23.y,
                                           b45.x, b45.y, b67.x, b67.y};
#pragma unroll
                for (int q = 0; q < 8; q++) {
                    FMA2(acc[0][q], a01.x, b[q], acc[0][q]);
                    FMA2(acc[1][q], a01.y, b[q], acc[1][q]);
                    FMA2(acc[2][q], a23.x, b[q], acc[2][q]);
                    FMA2(acc[3][q], a23.y, b[q], acc[3][q]);
                }
            }
        }
#undef LOADT

        float bv[8];
#pragma unroll
        for (int q = 0; q < 8; q++) {
            int gc = col0 + tc * 8 + q;
            bv[q] = (gc < 300) ? bias[gc] : 0.f;
        }
#pragma unroll
        for (int p = 0; p < 4; p++) {
            int rr = row0 + tr * 8 + 2 * p;
#pragma unroll
            for (int q = 0; q < 8; q++) {
                int gc = col0 + tc * 8 + q;
                if (gc < 300) {
                    float2 v = unpack2(acc[p][q]);
                    g_X[(long)rr * 300 + gc]       = v.x + bv[q];
                    g_X[(long)(rr + 1) * 300 + gc] = v.y + bv[q];
                }
            }
        }
        __threadfence();
        __syncthreads();
        if (tid == 0) atomicAdd(&g_flag[mchunk], 1);
        return;
    }

    // ================= LSTM consumer (blocks 0..23) =================
    // Gate-interleaved: thread p owns original gate column
    //   ocol = (p&3)*75 + (p>>2)   (r = gate {i,f,g,o}, j = hidden unit)
    // The 4 gates of unit j sit in adjacent lanes -> shuffle gather,
    // ONE __syncthreads per step.
    LstmSmem& L = *reinterpret_cast<LstmSmem*>(smbuf);
    const int m = blockIdx.x;
    const int p = tid;                // 0..319, active < 300
    const int r = p & 3;              // gate index: 0=i,1=f,2=g,3=o
    const int hj = p >> 2;            // hidden unit index
    const int ocol = r * 75 + hj;     // original gate column

    unsigned long long U2[38];
    if (p < G4) {
#pragma unroll
        for (int q = 0; q < 37; q++)
            U2[q] = pack2(U[(2 * q) * G4 + ocol], U[(2 * q + 1) * G4 + ocol]);
        U2[37] = pack2(U[74 * G4 + ocol], 0.0f);
    }
    if (p < 80) L.h[p] = 0.0f;
    float c = 0.0f;

    const float* xp = g_X + (long)m * G4 + ocol;
    int cur_chunk = -1;

#define WAIT_CHUNKS(need_) do {                                               \
        int _need = (need_);                                                  \
        if (_need > cur_chunk) {                                              \
            if (p == 0) {                                                     \
                volatile int* f = g_flag;                                     \
                for (int ch = cur_chunk + 1; ch <= _need; ++ch)               \
                    while (f[ch] < 2) {}                                      \
            }                                                                 \
            __threadfence();                                                  \
            __syncthreads();                                                  \
            cur_chunk = _need;                                                \
        }                                                                     \
    } while (0)

    // prologue: fill PF-deep register pipeline (steps 0..PF-1)
    WAIT_CHUNKS(((PF - 1) * LSTM_B + (LSTM_B - 1)) >> 7);
    float xbuf[PF];
#pragma unroll
    for (int q = 0; q < PF; q++)
        xbuf[q] = (p < G4) ? xp[(long)q * (LSTM_B * G4)] : 0.0f;

    for (int t0 = 0; t0 < NSEQ; t0 += PF) {
        int lastload = t0 + 2 * PF - 1;
        if (lastload >= NSEQ) lastload = NSEQ - 1;
        WAIT_CHUNKS((lastload * LSTM_B + (LSTM_B - 1)) >> 7);

#pragma unroll
        for (int jj = 0; jj < PF; jj++) {
            const int t = t0 + jj;

            float xnew = 0.0f;
            if (t + PF < NSEQ && p < G4)
                xnew = xp[(long)(t + PF) * (LSTM_B * G4)];
            const float xv = xbuf[jj];

            float a = 0.0f;
            if (p < G4) {
                const ulonglong2* h2 = (const ulonglong2*)L.h;
                unsigned long long a0 = 0ull, a1 = 0ull, a2 = 0ull, a3 = 0ull;
#pragma unroll
                for (int q = 0; q < 19; q += 2) {
                    ulonglong2 hv = h2[q];
                    FMA2(a0, hv.x, U2[2 * q],     a0);
                    FMA2(a1, hv.y, U2[2 * q + 1], a1);
                }
#pragma unroll
                for (int q = 1; q < 19; q += 2) {
                    ulonglong2 hv = h2[q];
                    FMA2(a2, hv.x, U2[2 * q],     a2);
                    FMA2(a3, hv.y, U2[2 * q + 1], a3);
                }
                ADD2(a0, a0, a1);
                ADD2(a2, a2, a3);
                ADD2(a0, a0, a2);
                float2 zz = unpack2(a0);
                float z = xv + zz.x + zz.y;
                a = (r == 2) ? tanhf_(z) : sigmoidf_(z);
            }

            // gather the other 3 gates of unit hj from adjacent lanes
            float x1 = __shfl_xor_sync(0xffffffffu, a, 1);
            float x2 = __shfl_xor_sync(0xffffffffu, a, 2);
            float x3 = __shfl_xor_sync(0xffffffffu, a, 3);

            if (p < G4) {
                // value of gate q is at lane with r==q
                float ai = (r == 0) ? a : (r == 1) ? x1 : (r == 2) ? x2 : x3;
                float af = (r == 1) ? a : (r == 0) ? x1 : (r == 3) ? x2 : x3;
                float ag = (r == 2) ? a : (r == 3) ? x1 : (r == 0) ? x2 : x3;
                float ao = (r == 3) ? a : (r == 2) ? x1 : (r == 1) ? x2 : x3;
                c = af * c + ai * ag;           // redundant in 4 lanes
                float h = ao * tanhf_(c);
                if (r == 0) {
                    L.h[hj] = h;
                    if ((t % 18) >= 12)   // only steps ctx_kernel reads
                        g_H[(long)t * (LSTM_B * H_LSTM) + m * H_LSTM + hj] = h;
                }
            }
            __syncthreads();                   // ONE barrier per step
            xbuf[jj] = xnew;
        }
    }
#undef WAIT_CHUNKS
}

// =====================================================================
// K3: ctx (u=2 row only)
// =====================================================================
__global__ __launch_bounds__(128) void ctx_kernel(
    const float* __restrict__ Wtw,    // 75 x 300
    const float* __restrict__ btw,    // 300
    const float* __restrict__ Atw,    // 6
    const float* __restrict__ Btw,    // 1
    const float* __restrict__ in)     // inputs
{
    const int t = blockIdx.x;         // 0..255
    const int tid = threadIdx.x;

    __shared__ float mv[H_LSTM];

    if (tid < H_LSTM) {
        float acc = 0.0f;
#pragma unroll
        for (int nn = 0; nn < NT1; nn++) {
            int s = (t * 3 + 2) * 6 + nn;
            const float* hp = g_H + (long)s * (LSTM_B * H_LSTM) + tid;
            float sm = 0.0f;
#pragma unroll
            for (int mm = 0; mm < LSTM_B; mm++) sm += hp[mm * H_LSTM];
            acc += Atw[nn] * sm;
        }
        mv[tid] = acc * (1.0f / 24.0f);
    }
    __syncthreads();

    float sumA = 0.0f;
#pragma unroll
    for (int nn = 0; nn < NT1; nn++) sumA += Atw[nn];
    const float B0 = Btw[0];
    const float c1 = 1000.0f / 1001.0f;

    for (int f = tid; f < WE; f += blockDim.x) {
        float acc = 0.0f;
#pragma unroll
        for (int j = 0; j < H_LSTM; j++) acc += mv[j] * Wtw[j * WE + f];
        g_ctx[t * CTXF + f] = c1 * (acc + sumA * btw[f]) + B0;
    }
    for (int q = tid; q < TE; q += blockDim.x) {
        float acc = 0.0f;
#pragma unroll
        for (int nn = 0; nn < NT1; nn++) {
            int s = (t * 3 + 2) * 6 + nn;
            acc += Atw[nn] * in[(long)s * D_IN + SL * WE + q];
        }
        g_ctx[t * CTXF + WE + q] = acc * (1.0f / 1001.0f) + B0;
    }
}

// =====================================================================
// K4: XG[t][n] = ctx[t] . gru_W[:,n] + gru_b[0][n]
// =====================================================================
__global__ __launch_bounds__(256) void xg_kernel(
    const float* __restrict__ gruW,   // 310 x 231
    const float* __restrict__ grub)   // 2 x 231
{
    const int t = blockIdx.x;
    const int tid = threadIdx.x;
    __shared__ float xs[CTXF];
    for (int i = tid; i < CTXF; i += blockDim.x) xs[i] = g_ctx[t * CTXF + i];
    __syncthreads();
    for (int nn = tid; nn < G3; nn += blockDim.x) {
        float acc = grub[nn];
        for (int k = 0; k < CTXF; k++) acc += xs[k] * gruW[k * G3 + nn];
        g_XG[t * G3 + nn] = acc;
    }
}

// =====================================================================
// K5: GRU recurrence (single 256-step sequence), k-packed f32x2.
// =====================================================================
__global__ __launch_bounds__(256, 1) void gru_kernel(
    const float* __restrict__ gruU,   // 77 x 231
    const float* __restrict__ grub)   // 2 x 231
{
    const int n = threadIdx.x;        // 0..255 (active < 231)

    __shared__ __align__(16) float h_s[80];
    __shared__ float rg_s[G3];

    unsigned long long U2[40];
    float b1n = 0.0f;
    if (n < G3) {
#pragma unroll
        for (int q = 0; q < 38; q++)
            U2[q] = pack2(gruU[(2 * q) * G3 + n], gruU[(2 * q + 1) * G3 + n]);
        U2[38] = pack2(gruU[76 * G3 + n], 0.0f);
        U2[39] = 0ull;
        b1n = grub[G3 + n];
    }
    if (n < 80) h_s[n] = 0.0f;
    __syncthreads();

    for (int t = 0; t < BATCH; t++) {
        if (n < G3) {
            const ulonglong2* h2 = (const ulonglong2*)h_s;
            unsigned long long a0 = 0ull, a1 = 0ull, a2 = 0ull, a3 = 0ull;
#pragma unroll
            for (int q = 0; q < 20; q += 2) {
                ulonglong2 hv = h2[q];
                FMA2(a0, hv.x, U2[2 * q],     a0);
                FMA2(a1, hv.y, U2[2 * q + 1], a1);
            }
#pragma unroll
            for (int q = 1; q < 20; q += 2) {
                ulonglong2 hv = h2[q];
                FMA2(a2, hv.x, U2[2 * q],     a2);
                FMA2(a3, hv.y, U2[2 * q + 1], a3);
            }
            ADD2(a0, a0, a1);
            ADD2(a2, a2, a3);
            ADD2(a0, a0, a2);
            float2 zz = unpack2(a0);
            rg_s[n] = b1n + zz.x + zz.y;
        }
        __syncthreads();

        if (n < H_GRU) {
            float xz = g_XG[t * G3 + n];
            float xr = g_XG[t * G3 + H_GRU + n];
            float xh = g_XG[t * G3 + 2 * H_GRU + n];
            float z = sigmoidf_(xz + rg_s[n]);
            float rr = sigmoidf_(xr + rg_s[H_GRU + n]);
            float hh = tanhf_(xh + rr * rg_s[2 * H_GRU + n]);
            float hold = h_s[n];
            float h = z * hold + (1.0f - z) * hh;
            h_s[n] = h;
            g_seqlast[t * H_GRU + n] = h;
        }
        __syncthreads();
    }
}

// =====================================================================
// K6: logits + softmax
// =====================================================================
__global__ __launch_bounds__(32) void out_kernel(
    const float* __restrict__ linW,   // 77 x 27
    const float* __restrict__ linb,   // 27
    float* __restrict__ out)          // 256 x 27
{
    const int t = blockIdx.x;
    const int c = threadIdx.x;        // 0..31 (active < 27)

    float logit = 0.0f;
    if (c < CLS) {
        logit = linb[c];
        const float* hp = g_seqlast + t * H_GRU;
#pragma unroll
        for (int k = 0; k < H_GRU; k++) logit += hp[k] * linW[k * CLS + c];
    }

    float x = (c < CLS) ? logit : -3.4e38f;
    float mx = x;
#pragma unroll
    for (int off = 16; off > 0; off >>= 1)
        mx = fmaxf(mx, __shfl_xor_sync(0xffffffffu, mx, off));
    float e = (c < CLS) ? __expf(logit - mx) : 0.0f;
    float s = e;
#pragma unroll
    for (int off = 16; off > 0; off >>= 1)
        s += __shfl_xor_sync(0xffffffffu, s, off);
    if (c < CLS) out[t * CLS + c] = e / s;
}

// =====================================================================
extern "C" void kernel_launch(void* const* d_in, const int* in_sizes, int n_in,
                              void* d_out, int out_size)
{
    (void)in_sizes; (void)n_in; (void)out_size;
    const float* inputs   = (const float*)d_in[0];
    const float* lstm_W   = (const float*)d_in[1];
    const float* lstm_U   = (const float*)d_in[2];
    const float* lstm_b   = (const float*)d_in[3];
    const float* lin_tw_W = (const float*)d_in[4];
    const float* lin_tw_b = (const float*)d_in[5];
    const float* A_tweets = (const float*)d_in[6];
    const float* B_tweets = (const float*)d_in[7];
    const float* gru_W    = (const float*)d_in[8];
    const float* gru_U    = (const float*)d_in[9];
    const float* gru_b    = (const float*)d_in[10];
    const float* lin_W    = (const float*)d_in[11];
    const float* lin_b    = (const float*)d_in[12];
    float* out = (float*)d_out;

    // Launch order places fused_kernel 4th — the slot ncu has been
    // capturing every round — so next profile shows the hot kernel.
    init_flags_kernel<<<1, MCHUNKS>>>();
    dummy_kernel<<<1, 32>>>();
    dummy_kernel<<<1, 32>>>();
    fused_kernel<<<LSTM_B + NBLK_GEMM, 320>>>(inputs, lstm_W, lstm_b, lstm_U);
    ctx_kernel<<<256, 128>>>(lin_tw_W, lin_tw_b, A_tweets, B_tweets, inputs);
    xg_kernel<<<256, 256>>>(gru_W, gru_b);
    gru_kernel<<<1, 256>>>(gru_U, gru_b);
    out_kernel<<<256, 32>>>(lin_W, lin_b, out);
}

// round 11
// speedup vs baseline: 1.2636x; 1.2636x over previous
#include <cuda_runtime.h>
#include <math.h>

// ---------------- Problem constants ----------------
#define WE 300
#define TE 10
#define SL 24
#define NT1 6
#define UT 3
#define H_LSTM 75          // WE/4
#define H_GRU 77           // (WE+TE)/4
#define CLS 27
#define D_IN 7210          // SL*WE + TE
#define BATCH 256
#define NSEQ 4608          // LSTM scan length
#define LSTM_B 24          // independent LSTM sequences
#define G4 300             // 4*H_LSTM
#define G3 231             // 3*H_GRU
#define CTXF 310           // WE+TE

// GEMM tiling
#define BM 128
#define BN 160
#define BK 20
#define NKT 15             // 300 / 20, exact
#define MCHUNKS 864        // 110592 / 128
#define NBLK_GEMM 1728     // MCHUNKS * 2

// LSTM X-prefetch depth (register ring, unrolled)
#define PF 8               // 4608 % 8 == 0

// ---------------- Scratch ----------------
__device__ float g_X[(long)NSEQ * LSTM_B * G4];     // ~132.7 MB
__device__ float g_H[(long)NSEQ * LSTM_B * H_LSTM]; // only t%18>=12 written
__device__ float g_ctx[BATCH * CTXF];
__device__ float g_XG[BATCH * G3];
__device__ float g_seqlast[BATCH * H_GRU];
__device__ int   g_flag[MCHUNKS];                   // per-M-chunk done count (target 2)

// ---------------- f32x2 packed helpers ----------------
__device__ __forceinline__ unsigned long long pack2(float lo, float hi) {
    unsigned long long r;
    asm("mov.b64 %0, {%1, %2};" : "=l"(r) : "f"(lo), "f"(hi));
    return r;
}
__device__ __forceinline__ float2 unpack2(unsigned long long v) {
    float2 f;
    asm("mov.b64 {%0, %1}, %2;" : "=f"(f.x), "=f"(f.y) : "l"(v));
    return f;
}
#define FMA2(d, a, b, c) \
    asm("fma.rn.f32x2 %0, %1, %2, %3;" : "=l"(d) : "l"(a), "l"(b), "l"(c))
#define ADD2(d, a, b) \
    asm("add.rn.f32x2 %0, %1, %2;" : "=l"(d) : "l"(a), "l"(b))

// ---------------- Activations ----------------
// Fast path (LSTM only): single-MUFU tanh.approx (|err| <= ~5e-4).
__device__ __forceinline__ float tanh_fast(float x) {
    float r;
    asm("tanh.approx.f32 %0, %1;" : "=f"(r) : "f"(x));
    return r;
}
__device__ __forceinline__ float sigmoid_fast(float x) {
    return fmaf(0.5f, tanh_fast(0.5f * x), 0.5f);
}
// Precise-ish path (GRU / softmax inputs).
__device__ __forceinline__ float sigmoidf_(float x) {
    return __fdividef(1.0f, 1.0f + __expf(-x));
}
__device__ __forceinline__ float tanhf_(float x) {
    return __fdividef(2.0f, 1.0f + __expf(-2.0f * x)) - 1.0f;
}

// ---------------- Flag reset ----------------
__global__ void init_flags_kernel() {
    if (threadIdx.x < MCHUNKS) g_flag[threadIdx.x] = 0;
}

// ---------------- Dummy (keeps fused kernel in ncu's capture slot) -------
__global__ void dummy_kernel() {}

// ---------------- Shared-memory overlays ----------------
struct GemmSmem {
    unsigned long long Bs2[BK][BN];   // B dup'd {b,b}: 25600 B
    float As[BK][BM];                 // A transposed [k][m]: 10240 B
};
struct LstmSmem {
    float h[80];                      // h[75..79] stay 0
};

// =====================================================================
// FUSED kernel: blocks 0..23 = LSTM consumers, blocks 24.. = GEMM.
// GEMM B-fragment now strided (tc + 20j) -> conflict-free LDS.64.
// LSTM uses tanh.approx activations + shfl.idx gate gather.
// =====================================================================
__global__ __launch_bounds__(320, 1) void fused_kernel(
    const float* __restrict__ A,      // inputs
    const float* __restrict__ W,      // lstm_W 300x300
    const float* __restrict__ bias,   // lstm_b 300
    const float* __restrict__ U)      // lstm_U 75x300
{
    __shared__ __align__(16) char smbuf[sizeof(GemmSmem)];
    const int tid = threadIdx.x;

    if (blockIdx.x >= LSTM_B) {
        // ================= GEMM producer =================
        GemmSmem& G = *reinterpret_cast<GemmSmem*>(smbuf);
        const int g = blockIdx.x - LSTM_B;
        const int mchunk = g >> 1;
        const int row0 = mchunk * BM;
        const int col0 = (g & 1) * BN;    // 0 or 160
        const int tr = tid / 20;          // 0..15 -> 8 M rows (4 pairs)
        const int tc = tid % 20;          // 0..19 -> 8 N cols (strided by 20)

        long abase[4]; int acol[4]; int arow_s[4];
#pragma unroll
        for (int i = 0; i < 4; i++) {
            int idx = tid + i * 320;
            arow_s[i] = idx / 10;
            int rr = row0 + arow_s[i];
            abase[i] = (long)rr * 300 + (rr / 24) * 10;
            acol[i]  = (idx % 10) * 2;
        }
        int bkk[5], bnn[5];
#pragma unroll
        for (int i = 0; i < 5; i++) {
            int idx = tid + i * 320;
            bkk[i] = idx / 80;
            bnn[i] = (idx % 80) * 2;
        }

        unsigned long long acc[4][8];
#pragma unroll
        for (int p = 0; p < 4; p++)
#pragma unroll
            for (int q = 0; q < 8; q++) acc[p][q] = 0ull;

        float2 Ar[4], Br[5];
#define LOADT(K0) do {                                                        \
        _Pragma("unroll")                                                     \
        for (int i = 0; i < 4; i++)                                           \
            Ar[i] = *(const float2*)(A + abase[i] + (K0) + acol[i]);          \
        _Pragma("unroll")                                                     \
        for (int i = 0; i < 5; i++) {                                         \
            int gc = col0 + bnn[i];                                           \
            Br[i] = (gc < 300)                                                \
                  ? *(const float2*)(W + (long)((K0) + bkk[i]) * 300 + gc)    \
                  : make_float2(0.f, 0.f);                                    \
        }                                                                     \
    } while (0)

        LOADT(0);
        for (int kt = 0; kt < NKT; kt++) {
            __syncthreads();
#pragma unroll
            for (int i = 0; i < 4; i++) {
                G.As[acol[i]][arow_s[i]]     = Ar[i].x;
                G.As[acol[i] + 1][arow_s[i]] = Ar[i].y;
            }
#pragma unroll
            for (int i = 0; i < 5; i++) {
                G.Bs2[bkk[i]][bnn[i]]     = pack2(Br[i].x, Br[i].x);
                G.Bs2[bkk[i]][bnn[i] + 1] = pack2(Br[i].y, Br[i].y);
            }
            __syncthreads();
            if (kt + 1 < NKT) LOADT((kt + 1) * BK);

#pragma unroll
            for (int kk = 0; kk < BK; kk++) {
                ulonglong2 a01 = *(const ulonglong2*)&G.As[kk][tr * 8];
                ulonglong2 a23 = *(const ulonglong2*)&G.As[kk][tr * 8 + 4];
                unsigned long long b[8];
#pragma unroll
                for (int q = 0; q < 8; q++)
                    b[q] = G.Bs2[kk][tc + 20 * q];   // conflict-free LDS.64
#pragma unroll
                for (int q = 0; q < 8; q++) {
                    FMA2(acc[0][q], a01.x, b[q], acc[0][q]);
                    FMA2(acc[1][q], a01.y, b[q], acc[1][q]);
                    FMA2(acc[2][q], a23.x, b[q], acc[2][q]);
                    FMA2(acc[3][q], a23.y, b[q], acc[3][q]);
                }
            }
        }
#undef LOADT

        float bv[8];
#pragma unroll
        for (int q = 0; q < 8; q++) {
            int gc = col0 + tc + 20 * q;
            bv[q] = (gc < 300) ? bias[gc] : 0.f;
        }
#pragma unroll
        for (int p = 0; p < 4; p++) {
            int rr = row0 + tr * 8 + 2 * p;
#pragma unroll
            for (int q = 0; q < 8; q++) {
                int gc = col0 + tc + 20 * q;
                if (gc < 300) {
                    float2 v = unpack2(acc[p][q]);
                    g_X[(long)rr * 300 + gc]       = v.x + bv[q];
                    g_X[(long)(rr + 1) * 300 + gc] = v.y + bv[q];
                }
            }
        }
        __threadfence();
        __syncthreads();
        if (tid == 0) atomicAdd(&g_flag[mchunk], 1);
        return;
    }

    // ================= LSTM consumer (blocks 0..23) =================
    // Gate-interleaved: thread p owns original gate column
    //   ocol = (p&3)*75 + (p>>2).  4 gates of unit j in adjacent lanes.
    LstmSmem& L = *reinterpret_cast<LstmSmem*>(smbuf);
    const int m = blockIdx.x;
    const int p = tid;                // 0..319, active < 300
    const int r = p & 3;              // gate index: 0=i,1=f,2=g,3=o
    const int hj = p >> 2;            // hidden unit index
    const int ocol = r * 75 + hj;     // original gate column
    const int lb = (p & 31) & ~3;     // lane base of the 4-gate group

    unsigned long long U2[38];
    if (p < G4) {
#pragma unroll
        for (int q = 0; q < 37; q++)
            U2[q] = pack2(U[(2 * q) * G4 + ocol], U[(2 * q + 1) * G4 + ocol]);
        U2[37] = pack2(U[74 * G4 + ocol], 0.0f);
    }
    if (p < 80) L.h[p] = 0.0f;
    float c = 0.0f;

    const float* xp = g_X + (long)m * G4 + ocol;
    int cur_chunk = -1;

#define WAIT_CHUNKS(need_) do {                                               \
        int _need = (need_);                                                  \
        if (_need > cur_chunk) {                                              \
            if (p == 0) {                                                     \
                volatile int* f = g_flag;                                     \
                for (int ch = cur_chunk + 1; ch <= _need; ++ch)               \
                    while (f[ch] < 2) {}                                      \
            }                                                                 \
            __threadfence();                                                  \
            __syncthreads();                                                  \
            cur_chunk = _need;                                                \
        }                                                                     \
    } while (0)

    WAIT_CHUNKS(((PF - 1) * LSTM_B + (LSTM_B - 1)) >> 7);
    float xbuf[PF];
#pragma unroll
    for (int q = 0; q < PF; q++)
        xbuf[q] = (p < G4) ? xp[(long)q * (LSTM_B * G4)] : 0.0f;

    for (int t0 = 0; t0 < NSEQ; t0 += PF) {
        int lastload = t0 + 2 * PF - 1;
        if (lastload >= NSEQ) lastload = NSEQ - 1;
        WAIT_CHUNKS((lastload * LSTM_B + (LSTM_B - 1)) >> 7);

#pragma unroll
        for (int jj = 0; jj < PF; jj++) {
            const int t = t0 + jj;

            float xnew = 0.0f;
            if (t + PF < NSEQ && p < G4)
                xnew = xp[(long)(t + PF) * (LSTM_B * G4)];
            const float xv = xbuf[jj];

            float a = 0.0f;
            if (p < G4) {
                const ulonglong2* h2 = (const ulonglong2*)L.h;
                unsigned long long a0 = 0ull, a1 = 0ull, a2 = 0ull, a3 = 0ull;
#pragma unroll
                for (int q = 0; q < 19; q += 2) {
                    ulonglong2 hv = h2[q];
                    FMA2(a0, hv.x, U2[2 * q],     a0);
                    FMA2(a1, hv.y, U2[2 * q + 1], a1);
                }
#pragma unroll
                for (int q = 1; q < 19; q += 2) {
                    ulonglong2 hv = h2[q];
                    FMA2(a2, hv.x, U2[2 * q],     a2);
                    FMA2(a3, hv.y, U2[2 * q + 1], a3);
                }
                ADD2(a0, a0, a1);
                ADD2(a2, a2, a3);
                ADD2(a0, a0, a2);
                float2 zz = unpack2(a0);
                float z = xv + zz.x + zz.y;
                a = (r == 2) ? tanh_fast(z) : sigmoid_fast(z);
            }

            // gather the 4 gates of unit hj via shfl.idx (no selects)
            float ai = __shfl_sync(0xffffffffu, a, lb + 0, 32);
            float af = __shfl_sync(0xffffffffu, a, lb + 1, 32);
            float ag = __shfl_sync(0xffffffffu, a, lb + 2, 32);
            float ao = __shfl_sync(0xffffffffu, a, lb + 3, 32);

            if (p < G4) {
                c = af * c + ai * ag;           // redundant in 4 lanes
                float h = ao * tanh_fast(c);
                if (r == 0) {
                    L.h[hj] = h;
                    if ((t % 18) >= 12)   // only steps ctx_kernel reads
                        g_H[(long)t * (LSTM_B * H_LSTM) + m * H_LSTM + hj] = h;
                }
            }
            __syncthreads();                   // ONE barrier per step
            xbuf[jj] = xnew;
        }
    }
#undef WAIT_CHUNKS
}

// =====================================================================
// K3: ctx (u=2 row only)
// =====================================================================
__global__ __launch_bounds__(128) void ctx_kernel(
    const float* __restrict__ Wtw,    // 75 x 300
    const float* __restrict__ btw,    // 300
    const float* __restrict__ Atw,    // 6
    const float* __restrict__ Btw,    // 1
    const float* __restrict__ in)     // inputs
{
    const int t = blockIdx.x;         // 0..255
    const int tid = threadIdx.x;

    __shared__ float mv[H_LSTM];

    if (tid < H_LSTM) {
        float acc = 0.0f;
#pragma unroll
        for (int nn = 0; nn < NT1; nn++) {
            int s = (t * 3 + 2) * 6 + nn;
            const float* hp = g_H + (long)s * (LSTM_B * H_LSTM) + tid;
            float sm = 0.0f;
#pragma unroll
            for (int mm = 0; mm < LSTM_B; mm++) sm += hp[mm * H_LSTM];
            acc += Atw[nn] * sm;
        }
        mv[tid] = acc * (1.0f / 24.0f);
    }
    __syncthreads();

    float sumA = 0.0f;
#pragma unroll
    for (int nn = 0; nn < NT1; nn++) sumA += Atw[nn];
    const float B0 = Btw[0];
    const float c1 = 1000.0f / 1001.0f;

    for (int f = tid; f < WE; f += blockDim.x) {
        float acc = 0.0f;
#pragma unroll
        for (int j = 0; j < H_LSTM; j++) acc += mv[j] * Wtw[j * WE + f];
        g_ctx[t * CTXF + f] = c1 * (acc + sumA * btw[f]) + B0;
    }
    for (int q = tid; q < TE; q += blockDim.x) {
        float acc = 0.0f;
#pragma unroll
        for (int nn = 0; nn < NT1; nn++) {
            int s = (t * 3 + 2) * 6 + nn;
            acc += Atw[nn] * in[(long)s * D_IN + SL * WE + q];
        }
        g_ctx[t * CTXF + WE + q] = acc * (1.0f / 1001.0f) + B0;
    }
}

// =====================================================================
// K4: XG[t][n] = ctx[t] . gru_W[:,n] + gru_b[0][n]
// =====================================================================
__global__ __launch_bounds__(256) void xg_kernel(
    const float* __restrict__ gruW,   // 310 x 231
    const float* __restrict__ grub)   // 2 x 231
{
    const int t = blockIdx.x;
    const int tid = threadIdx.x;
    __shared__ float xs[CTXF];
    for (int i = tid; i < CTXF; i += blockDim.x) xs[i] = g_ctx[t * CTXF + i];
    __syncthreads();
    for (int nn = tid; nn < G3; nn += blockDim.x) {
        float acc = grub[nn];
        for (int k = 0; k < CTXF; k++) acc += xs[k] * gruW[k * G3 + nn];
        g_XG[t * G3 + nn] = acc;
    }
}

// =====================================================================
// K5: GRU recurrence (single 256-step sequence), k-packed f32x2.
// =====================================================================
__global__ __launch_bounds__(256, 1) void gru_kernel(
    const float* __restrict__ gruU,   // 77 x 231
    const float* __restrict__ grub)   // 2 x 231
{
    const int n = threadIdx.x;        // 0..255 (active < 231)

    __shared__ __align__(16) float h_s[80];
    __shared__ float rg_s[G3];

    unsigned long long U2[40];
    float b1n = 0.0f;
    if (n < G3) {
#pragma unroll
        for (int q = 0; q < 38; q++)
            U2[q] = pack2(gruU[(2 * q) * G3 + n], gruU[(2 * q + 1) * G3 + n]);
        U2[38] = pack2(gruU[76 * G3 + n], 0.0f);
        U2[39] = 0ull;
        b1n = grub[G3 + n];
    }
    if (n < 80) h_s[n] = 0.0f;
    __syncthreads();

    for (int t = 0; t < BATCH; t++) {
        if (n < G3) {
            const ulonglong2* h2 = (const ulonglong2*)h_s;
            unsigned long long a0 = 0ull, a1 = 0ull, a2 = 0ull, a3 = 0ull;
#pragma unroll
            for (int q = 0; q < 20; q += 2) {
                ulonglong2 hv = h2[q];
                FMA2(a0, hv.x, U2[2 * q],     a0);
                FMA2(a1, hv.y, U2[2 * q + 1], a1);
            }
#pragma unroll
            for (int q = 1; q < 20; q += 2) {
                ulonglong2 hv = h2[q];
                FMA2(a2, hv.x, U2[2 * q],     a2);
                FMA2(a3, hv.y, U2[2 * q + 1], a3);
            }
            ADD2(a0, a0, a1);
            ADD2(a2, a2, a3);
            ADD2(a0, a0, a2);
            float2 zz = unpack2(a0);
            rg_s[n] = b1n + zz.x + zz.y;
        }
        __syncthreads();

        if (n < H_GRU) {
            float xz = g_XG[t * G3 + n];
            float xr = g_XG[t * G3 + H_GRU + n];
            float xh = g_XG[t * G3 + 2 * H_GRU + n];
            float z = sigmoidf_(xz + rg_s[n]);
            float rr = sigmoidf_(xr + rg_s[H_GRU + n]);
            float hh = tanhf_(xh + rr * rg_s[2 * H_GRU + n]);
            float hold = h_s[n];
            float h = z * hold + (1.0f - z) * hh;
            h_s[n] = h;
            g_seqlast[t * H_GRU + n] = h;
        }
        __syncthreads();
    }
}

// =====================================================================
// K6: logits + softmax
// =====================================================================
__global__ __launch_bounds__(32) void out_kernel(
    const float* __restrict__ linW,   // 77 x 27
    const float* __restrict__ linb,   // 27
    float* __restrict__ out)          // 256 x 27
{
    const int t = blockIdx.x;
    const int c = threadIdx.x;        // 0..31 (active < 27)

    float logit = 0.0f;
    if (c < CLS) {
        logit = linb[c];
        const float* hp = g_seqlast + t * H_GRU;
#pragma unroll
        for (int k = 0; k < H_GRU; k++) logit += hp[k] * linW[k * CLS + c];
    }

    float x = (c < CLS) ? logit : -3.4e38f;
    float mx = x;
#pragma unroll
    for (int off = 16; off > 0; off >>= 1)
        mx = fmaxf(mx, __shfl_xor_sync(0xffffffffu, mx, off));
    float e = (c < CLS) ? __expf(logit - mx) : 0.0f;
    float s = e;
#pragma unroll
    for (int off = 16; off > 0; off >>= 1)
        s += __shfl_xor_sync(0xffffffffu, s, off);
    if (c < CLS) out[t * CLS + c] = e / s;
}

// =====================================================================
extern "C" void kernel_launch(void* const* d_in, const int* in_sizes, int n_in,
                              void* d_out, int out_size)
{
    (void)in_sizes; (void)n_in; (void)out_size;
    const float* inputs   = (const float*)d_in[0];
    const float* lstm_W   = (const float*)d_in[1];
    const float* lstm_U   = (const float*)d_in[2];
    const float* lstm_b   = (const float*)d_in[3];
    const float* lin_tw_W = (const float*)d_in[4];
    const float* lin_tw_b = (const float*)d_in[5];
    const float* A_tweets = (const float*)d_in[6];
    const float* B_tweets = (const float*)d_in[7];
    const float* gru_W    = (const float*)d_in[8];
    const float* gru_U    = (const float*)d_in[9];
    const float* gru_b    = (const float*)d_in[10];
    const float* lin_W    = (const float*)d_in[11];
    const float* lin_b    = (const float*)d_in[12];
    float* out = (float*)d_out;

    init_flags_kernel<<<1, MCHUNKS>>>();
    dummy_kernel<<<1, 32>>>();
    dummy_kernel<<<1, 32>>>();
    fused_kernel<<<LSTM_B + NBLK_GEMM, 320>>>(inputs, lstm_W, lstm_b, lstm_U);
    ctx_kernel<<<256, 128>>>(lin_tw_W, lin_tw_b, A_tweets, B_tweets, inputs);
    xg_kernel<<<256, 256>>>(gru_W, gru_b);
    gru_kernel<<<1, 256>>>(gru_U, gru_b);
    out_kernel<<<256, 32>>>(lin_W, lin_b, out);
}

// round 12
// speedup vs baseline: 1.3161x; 1.0416x over previous
#include <cuda_runtime.h>
#include <math.h>

// ---------------- Problem constants ----------------
#define WE 300
#define TE 10
#define SL 24
#define NT1 6
#define UT 3
#define H_LSTM 75          // WE/4
#define H_GRU 77           // (WE+TE)/4
#define CLS 27
#define D_IN 7210          // SL*WE + TE
#define BATCH 256
#define NSEQ 4608          // LSTM scan length
#define LSTM_B 24          // independent LSTM sequences
#define G4 300             // 4*H_LSTM
#define G3 231             // 3*H_GRU
#define CTXF 310           // WE+TE

// GEMM tiling
#define BM 128
#define BN 160
#define BK 20
#define NKT 15             // 300 / 20, exact
#define MCHUNKS 864        // 110592 / 128
#define NBLK_GEMM 1728     // MCHUNKS * 2

#define NTHR 640           // block size (20 warps)
#define PF 8               // LSTM X-prefetch depth (4608 % 8 == 0)

// ---------------- Scratch ----------------
__device__ float g_X[(long)NSEQ * LSTM_B * G4];     // ~132.7 MB
__device__ float g_H[(long)NSEQ * LSTM_B * H_LSTM]; // only t%18>=12 written
__device__ float g_ctx[BATCH * CTXF];
__device__ float g_XG[BATCH * G3];
__device__ float g_seqlast[BATCH * H_GRU];
__device__ int   g_flag[MCHUNKS];                   // per-M-chunk done count (target 2)

// ---------------- f32x2 packed helpers ----------------
__device__ __forceinline__ unsigned long long pack2(float lo, float hi) {
    unsigned long long r;
    asm("mov.b64 %0, {%1, %2};" : "=l"(r) : "f"(lo), "f"(hi));
    return r;
}
__device__ __forceinline__ float2 unpack2(unsigned long long v) {
    float2 f;
    asm("mov.b64 {%0, %1}, %2;" : "=f"(f.x), "=f"(f.y) : "l"(v));
    return f;
}
#define FMA2(d, a, b, c) \
    asm("fma.rn.f32x2 %0, %1, %2, %3;" : "=l"(d) : "l"(a), "l"(b), "l"(c))
#define ADD2(d, a, b) \
    asm("add.rn.f32x2 %0, %1, %2;" : "=l"(d) : "l"(a), "l"(b))

// ---------------- Activations ----------------
__device__ __forceinline__ float tanh_fast(float x) {
    float r;
    asm("tanh.approx.f32 %0, %1;" : "=f"(r) : "f"(x));
    return r;
}
__device__ __forceinline__ float sigmoid_fast(float x) {
    return fmaf(0.5f, tanh_fast(0.5f * x), 0.5f);
}
__device__ __forceinline__ float sigmoidf_(float x) {
    return __fdividef(1.0f, 1.0f + __expf(-x));
}
__device__ __forceinline__ float tanhf_(float x) {
    return __fdividef(2.0f, 1.0f + __expf(-2.0f * x)) - 1.0f;
}

// ---------------- Flag reset ----------------
__global__ void init_flags_kernel() {
    if (threadIdx.x < MCHUNKS) g_flag[threadIdx.x] = 0;
}

// ---------------- Dummy (keeps fused kernel in ncu's capture slot) -------
__global__ void dummy_kernel() {}

// ---------------- Shared-memory overlays ----------------
struct GemmSmem {
    unsigned long long Bs2[BK][BN];   // B dup'd {b,b}: 25600 B
    float As[BK][BM];                 // A transposed [k][m]: 10240 B
};
struct LstmSmem {
    float h[2][80];                   // double-buffered; [*][75..79] stay 0
};

// =====================================================================
// FUSED kernel, 640 threads/block.
//   blocks 0..23  : LSTM. Each gate column's 75-dot split across an
//                   even/odd lane pair (k<40 / k>=40), combined with one
//                   shfl.xor. 19 active warps -> 5/SMSP: same issue
//                   count as before but 2x latency hiding and half the
//                   FMA chain depth. h ping-pong buffered (no WAR race).
//   blocks 24..   : GEMM producers, re-tiled 2 M-pairs x 8 N per thread.
// =====================================================================
__global__ __launch_bounds__(NTHR, 1) void fused_kernel(
    const float* __restrict__ A,      // inputs
    const float* __restrict__ W,      // lstm_W 300x300
    const float* __restrict__ bias,   // lstm_b 300
    const float* __restrict__ U)      // lstm_U 75x300
{
    __shared__ __align__(16) char smbuf[sizeof(GemmSmem)];
    const int tid = threadIdx.x;

    if (blockIdx.x >= LSTM_B) {
        // ================= GEMM producer =================
        GemmSmem& G = *reinterpret_cast<GemmSmem*>(smbuf);
        const int g = blockIdx.x - LSTM_B;
        const int mchunk = g >> 1;
        const int row0 = mchunk * BM;
        const int col0 = (g & 1) * BN;    // 0 or 160
        const int tr = tid / 20;          // 0..31 -> 4 M rows (2 pairs)
        const int tc = tid % 20;          // 0..19 -> 8 N cols (stride 20)

        // A-loader: 1280 float2 / 640 thr = 2 each
        long abase[2]; int acol[2]; int arow_s[2];
#pragma unroll
        for (int i = 0; i < 2; i++) {
            int idx = tid + i * NTHR;     // 0..1279
            arow_s[i] = idx / 10;
            int rr = row0 + arow_s[i];
            abase[i] = (long)rr * 300 + (rr / 24) * 10;
            acol[i]  = (idx % 10) * 2;
        }
        // B-loader: 1600 float2 -> 3 each with guard
        int bkk[3], bnn[3]; bool bok[3];
#pragma unroll
        for (int i = 0; i < 3; i++) {
            int idx = tid + i * NTHR;     // 0..1919
            bok[i] = (idx < 1600);
            int ix = bok[i] ? idx : 0;
            bkk[i] = ix / 80;
            bnn[i] = (ix % 80) * 2;
        }

        unsigned long long acc[2][8];
#pragma unroll
        for (int p = 0; p < 2; p++)
#pragma unroll
            for (int q = 0; q < 8; q++) acc[p][q] = 0ull;

        float2 Ar[2], Br[3];
#define LOADT(K0) do {                                                        \
        _Pragma("unroll")                                                     \
        for (int i = 0; i < 2; i++)                                           \
            Ar[i] = *(const float2*)(A + abase[i] + (K0) + acol[i]);          \
        _Pragma("unroll")                                                     \
        for (int i = 0; i < 3; i++) {                                         \
            int gc = col0 + bnn[i];                                           \
            Br[i] = (bok[i] && gc < 300)                                      \
                  ? *(const float2*)(W + (long)((K0) + bkk[i]) * 300 + gc)    \
                  : make_float2(0.f, 0.f);                                    \
        }                                                                     \
    } while (0)

        LOADT(0);
        for (int kt = 0; kt < NKT; kt++) {
            __syncthreads();
#pragma unroll
            for (int i = 0; i < 2; i++) {
                G.As[acol[i]][arow_s[i]]     = Ar[i].x;
                G.As[acol[i] + 1][arow_s[i]] = Ar[i].y;
            }
#pragma unroll
            for (int i = 0; i < 3; i++) {
                if (bok[i]) {
                    G.Bs2[bkk[i]][bnn[i]]     = pack2(Br[i].x, Br[i].x);
                    G.Bs2[bkk[i]][bnn[i] + 1] = pack2(Br[i].y, Br[i].y);
                }
            }
            __syncthreads();
            if (kt + 1 < NKT) LOADT((kt + 1) * BK);

#pragma unroll
            for (int kk = 0; kk < BK; kk++) {
                ulonglong2 a01 = *(const ulonglong2*)&G.As[kk][tr * 4];
                unsigned long long b[8];
#pragma unroll
                for (int q = 0; q < 8; q++)
                    b[q] = G.Bs2[kk][tc + 20 * q];   // near-conflict-free
#pragma unroll
                for (int q = 0; q < 8; q++) {
                    FMA2(acc[0][q], a01.x, b[q], acc[0][q]);
                    FMA2(acc[1][q], a01.y, b[q], acc[1][q]);
                }
            }
        }
#undef LOADT

        float bv[8];
#pragma unroll
        for (int q = 0; q < 8; q++) {
            int gc = col0 + tc + 20 * q;
            bv[q] = (gc < 300) ? bias[gc] : 0.f;
        }
#pragma unroll
        for (int p = 0; p < 2; p++) {
            int rr = row0 + tr * 4 + 2 * p;
#pragma unroll
            for (int q = 0; q < 8; q++) {
                int gc = col0 + tc + 20 * q;
                if (gc < 300) {
                    float2 v = unpack2(acc[p][q]);
                    g_X[(long)rr * 300 + gc]       = v.x + bv[q];
                    g_X[(long)(rr + 1) * 300 + gc] = v.y + bv[q];
                }
            }
        }
        __threadfence();
        __syncthreads();
        if (tid == 0) atomicAdd(&g_flag[mchunk], 1);
        return;
    }

    // ================= LSTM consumer (blocks 0..23) =================
    LstmSmem& L = *reinterpret_cast<LstmSmem*>(smbuf);
    const int m = blockIdx.x;
    const int col  = tid >> 1;        // gate column 0..319 (<300 active)
    const int half = tid & 1;         // k-half: 0 -> k<40, 1 -> k>=40
    if (col >= 304) return;           // warp 19 exits entirely
    const bool act = (col < 300);
    const int r  = col & 3;           // gate: 0=i,1=f,2=g,3=o
    const int hj = col >> 2;          // hidden unit
    const int ocol = r * 75 + hj;     // original gate column (valid iff act)
    const int lane = tid & 31;
    const int lb = lane & ~7;         // lane base of 8-lane unit group

    // U2: 20 k-pairs for this thread's half (rows >=75 zero-padded)
    unsigned long long U2[20];
#pragma unroll
    for (int q = 0; q < 20; q++) {
        int k0 = half * 40 + 2 * q;
        float u0 = (act && k0     < H_LSTM) ? U[k0 * G4 + ocol]       : 0.f;
        float u1 = (act && k0 + 1 < H_LSTM) ? U[(k0 + 1) * G4 + ocol] : 0.f;
        U2[q] = pack2(u0, u1);
    }
    if (tid < 80) { L.h[0][tid] = 0.f; L.h[1][tid] = 0.f; }
    float c = 0.0f;

    const float* xp = g_X + (act ? ((long)m * G4 + ocol) : 0);
    int cur_chunk = -1;

#define WAIT_CHUNKS(need_) do {                                               \
        int _need = (need_);                                                  \
        if (_need > cur_chunk) {                                              \
            if (tid == 0) {                                                   \
                volatile int* f = g_flag;                                     \
                for (int ch = cur_chunk + 1; ch <= _need; ++ch)               \
                    while (f[ch] < 2) {}                                      \
            }                                                                 \
            __threadfence();                                                  \
            __syncthreads();                                                  \
            cur_chunk = _need;                                                \
        }                                                                     \
    } while (0)

    WAIT_CHUNKS(((PF - 1) * LSTM_B + (LSTM_B - 1)) >> 7);
    float xbuf[PF];
#pragma unroll
    for (int q = 0; q < PF; q++)
        xbuf[q] = (half == 0 && act) ? xp[(long)q * (LSTM_B * G4)] : 0.0f;

    for (int t0 = 0; t0 < NSEQ; t0 += PF) {
        int lastload = t0 + 2 * PF - 1;
        if (lastload >= NSEQ) lastload = NSEQ - 1;
        WAIT_CHUNKS((lastload * LSTM_B + (LSTM_B - 1)) >> 7);

#pragma unroll
        for (int jj = 0; jj < PF; jj++) {
            const int t = t0 + jj;
            const int rb = jj & 1;    // read buffer (t0, PF even -> t&1)

            float xnew = 0.0f;
            if (half == 0 && act && t + PF < NSEQ)
                xnew = xp[(long)(t + PF) * (LSTM_B * G4)];
            const float xv = xbuf[jj];

            // half-dot: 20 FMA2 over this thread's 40 k-elements
            const ulonglong2* h2 =
                (const ulonglong2*)(&L.h[rb][half * 40]);
            unsigned long long a0, a1 = 0ull, a2 = 0ull, a3 = 0ull;
            a0 = (half == 0) ? pack2(xv, 0.0f) : 0ull;
#pragma unroll
            for (int q = 0; q < 10; q += 2) {
                ulonglong2 hv = h2[q];
                FMA2(a0, hv.x, U2[2 * q],     a0);
                FMA2(a1, hv.y, U2[2 * q + 1], a1);
            }
#pragma unroll
            for (int q = 1; q < 10; q += 2) {
                ulonglong2 hv = h2[q];
                FMA2(a2, hv.x, U2[2 * q],     a2);
                FMA2(a3, hv.y, U2[2 * q + 1], a3);
            }
            ADD2(a0, a0, a1);
            ADD2(a2, a2, a3);
            ADD2(a0, a0, a2);
            float2 zz = unpack2(a0);
            float zh = zz.x + zz.y;
            // combine the two k-halves (lanes tid, tid^1)
            float z = zh + __shfl_xor_sync(0xffffffffu, zh, 1);

            float a = (r == 2) ? tanh_fast(z) : sigmoid_fast(z);

            // gather the 4 gates of unit hj (8-lane group, even offsets)
            float ai = __shfl_sync(0xffffffffu, a, lb + 0, 32);
            float af = __shfl_sync(0xffffffffu, a, lb + 2, 32);
            float ag = __shfl_sync(0xffffffffu, a, lb + 4, 32);
            float ao = __shfl_sync(0xffffffffu, a, lb + 6, 32);

            c = af * c + ai * ag;     // redundant in 8 lanes
            float h = ao * tanh_fast(c);
            if ((tid & 7) == 0 && act) {
                L.h[rb ^ 1][hj] = h;  // write NEXT buffer: no WAR race
                if ((t % 18) >= 12)   // only steps ctx_kernel reads
                    g_H[(long)t * (LSTM_B * H_LSTM) + m * H_LSTM + hj] = h;
            }
            __syncthreads();          // one barrier per step
            xbuf[jj] = xnew;
        }
    }
#undef WAIT_CHUNKS
}

// =====================================================================
// K3: ctx (u=2 row only)
// =====================================================================
__global__ __launch_bounds__(128) void ctx_kernel(
    const float* __restrict__ Wtw,    // 75 x 300
    const float* __restrict__ btw,    // 300
    const float* __restrict__ Atw,    // 6
    const float* __restrict__ Btw,    // 1
    const float* __restrict__ in)     // inputs
{
    const int t = blockIdx.x;         // 0..255
    const int tid = threadIdx.x;

    __shared__ float mv[H_LSTM];

    if (tid < H_LSTM) {
        float acc = 0.0f;
#pragma unroll
        for (int nn = 0; nn < NT1; nn++) {
            int s = (t * 3 + 2) * 6 + nn;
            const float* hp = g_H + (long)s * (LSTM_B * H_LSTM) + tid;
            float sm = 0.0f;
#pragma unroll
            for (int mm = 0; mm < LSTM_B; mm++) sm += hp[mm * H_LSTM];
            acc += Atw[nn] * sm;
        }
        mv[tid] = acc * (1.0f / 24.0f);
    }
    __syncthreads();

    float sumA = 0.0f;
#pragma unroll
    for (int nn = 0; nn < NT1; nn++) sumA += Atw[nn];
    const float B0 = Btw[0];
    const float c1 = 1000.0f / 1001.0f;

    for (int f = tid; f < WE; f += blockDim.x) {
        float acc = 0.0f;
#pragma unroll
        for (int j = 0; j < H_LSTM; j++) acc += mv[j] * Wtw[j * WE + f];
        g_ctx[t * CTXF + f] = c1 * (acc + sumA * btw[f]) + B0;
    }
    for (int q = tid; q < TE; q += blockDim.x) {
        float acc = 0.0f;
#pragma unroll
        for (int nn = 0; nn < NT1; nn++) {
            int s = (t * 3 + 2) * 6 + nn;
            acc += Atw[nn] * in[(long)s * D_IN + SL * WE + q];
        }
        g_ctx[t * CTXF + WE + q] = acc * (1.0f / 1001.0f) + B0;
    }
}

// =====================================================================
// K4: XG[t][n] = ctx[t] . gru_W[:,n] + gru_b[0][n]
// =====================================================================
__global__ __launch_bounds__(256) void xg_kernel(
    const float* __restrict__ gruW,   // 310 x 231
    const float* __restrict__ grub)   // 2 x 231
{
    const int t = blockIdx.x;
    const int tid = threadIdx.x;
    __shared__ float xs[CTXF];
    for (int i = tid; i < CTXF; i += blockDim.x) xs[i] = g_ctx[t * CTXF + i];
    __syncthreads();
    for (int nn = tid; nn < G3; nn += blockDim.x) {
        float acc = grub[nn];
        for (int k = 0; k < CTXF; k++) acc += xs[k] * gruW[k * G3 + nn];
        g_XG[t * G3 + nn] = acc;
    }
}

// =====================================================================
// K5: GRU recurrence (single 256-step sequence), k-packed f32x2.
// =====================================================================
__global__ __launch_bounds__(256, 1) void gru_kernel(
    const float* __restrict__ gruU,   // 77 x 231
    const float* __restrict__ grub)   // 2 x 231
{
    const int n = threadIdx.x;        // 0..255 (active < 231)

    __shared__ __align__(16) float h_s[80];
    __shared__ float rg_s[G3];

    unsigned long long U2[40];
    float b1n = 0.0f;
    if (n < G3) {
#pragma unroll
        for (int q = 0; q < 38; q++)
            U2[q] = pack2(gruU[(2 * q) * G3 + n], gruU[(2 * q + 1) * G3 + n]);
        U2[38] = pack2(gruU[76 * G3 + n], 0.0f);
        U2[39] = 0ull;
        b1n = grub[G3 + n];
    }
    if (n < 80) h_s[n] = 0.0f;
    __syncthreads();

    for (int t = 0; t < BATCH; t++) {
        if (n < G3) {
            const ulonglong2* h2 = (const ulonglong2*)h_s;
            unsigned long long a0 = 0ull, a1 = 0ull, a2 = 0ull, a3 = 0ull;
#pragma unroll
            for (int q = 0; q < 20; q += 2) {
                ulonglong2 hv = h2[q];
                FMA2(a0, hv.x, U2[2 * q],     a0);
                FMA2(a1, hv.y, U2[2 * q + 1], a1);
            }
#pragma unroll
            for (int q = 1; q < 20; q += 2) {
                ulonglong2 hv = h2[q];
                FMA2(a2, hv.x, U2[2 * q],     a2);
                FMA2(a3, hv.y, U2[2 * q + 1], a3);
            }
            ADD2(a0, a0, a1);
            ADD2(a2, a2, a3);
            ADD2(a0, a0, a2);
            float2 zz = unpack2(a0);
            rg_s[n] = b1n + zz.x + zz.y;
        }
        __syncthreads();

        if (n < H_GRU) {
            float xz = g_XG[t * G3 + n];
            float xr = g_XG[t * G3 + H_GRU + n];
            float xh = g_XG[t * G3 + 2 * H_GRU + n];
            float z = sigmoidf_(xz + rg_s[n]);
            float rr = sigmoidf_(xr + rg_s[H_GRU + n]);
            float hh = tanhf_(xh + rr * rg_s[2 * H_GRU + n]);
            float hold = h_s[n];
            float h = z * hold + (1.0f - z) * hh;
            h_s[n] = h;
            g_seqlast[t * H_GRU + n] = h;
        }
        __syncthreads();
    }
}

// =====================================================================
// K6: logits + softmax
// =====================================================================
__global__ __launch_bounds__(32) void out_kernel(
    const float* __restrict__ linW,   // 77 x 27
    const float* __restrict__ linb,   // 27
    float* __restrict__ out)          // 256 x 27
{
    const int t = blockIdx.x;
    const int c = threadIdx.x;        // 0..31 (active < 27)

    float logit = 0.0f;
    if (c < CLS) {
        logit = linb[c];
        const float* hp = g_seqlast + t * H_GRU;
#pragma unroll
        for (int k = 0; k < H_GRU; k++) logit += hp[k] * linW[k * CLS + c];
    }

    float x = (c < CLS) ? logit : -3.4e38f;
    float mx = x;
#pragma unroll
    for (int off = 16; off > 0; off >>= 1)
        mx = fmaxf(mx, __shfl_xor_sync(0xffffffffu, mx, off));
    float e = (c < CLS) ? __expf(logit - mx) : 0.0f;
    float s = e;
#pragma unroll
    for (int off = 16; off > 0; off >>= 1)
        s += __shfl_xor_sync(0xffffffffu, s, off);
    if (c < CLS) out[t * CLS + c] = e / s;
}

// =====================================================================
extern "C" void kernel_launch(void* const* d_in, const int* in_sizes, int n_in,
                              void* d_out, int out_size)
{
    (void)in_sizes; (void)n_in; (void)out_size;
    const float* inputs   = (const float*)d_in[0];
    const float* lstm_W   = (const float*)d_in[1];
    const float* lstm_U   = (const float*)d_in[2];
    const float* lstm_b   = (const float*)d_in[3];
    const float* lin_tw_W = (const float*)d_in[4];
    const float* lin_tw_b = (const float*)d_in[5];
    const float* A_tweets = (const float*)d_in[6];
    const float* B_tweets = (const float*)d_in[7];
    const float* gru_W    = (const float*)d_in[8];
    const float* gru_U    = (const float*)d_in[9];
    const float* gru_b    = (const float*)d_in[10];
    const float* lin_W    = (const float*)d_in[11];
    const float* lin_b    = (const float*)d_in[12];
    float* out = (float*)d_out;

    init_flags_kernel<<<1, MCHUNKS>>>();
    dummy_kernel<<<1, 32>>>();
    dummy_kernel<<<1, 32>>>();
    fused_kernel<<<LSTM_B + NBLK_GEMM, NTHR>>>(inputs, lstm_W, lstm_b, lstm_U);
    ctx_kernel<<<256, 128>>>(lin_tw_W, lin_tw_b, A_tweets, B_tweets, inputs);
    xg_kernel<<<256, 256>>>(gru_W, gru_b);
    gru_kernel<<<1, 256>>>(gru_U, gru_b);
    out_kernel<<<256, 32>>>(lin_W, lin_b, out);
}